// round 8
// baseline (speedup 1.0000x reference)
#include <cuda_runtime.h>

#define NN   50000
#define C    128
#define E    800000
#define EF   65
#define EAC  70
#define ET   64

typedef unsigned long long ull;

// ---------------- scratch (device globals; no allocation allowed) ------------
__device__ float g_A [C*C];           // Wf1 + Wf3
__device__ float g_B [C*C];           // Wf2 - Wf3
__device__ float g_M [C*C];           // scale * Wq diag(Wa) Wk^T
__device__ float g_XA[NN*C];          // x @ A
__device__ float g_XB[NN*C];          // x @ B
__device__ float g_Xm[NN*C];          // x @ M
__device__ float g_asum[NN];          // segment sum of a over src
__device__ float g_aggr[NN*C];        // segment sum of exp(a)*f over src

// ---------------- packed fp32x2 helpers (Blackwell FFMA2) --------------------
__device__ __forceinline__ void fma2(ull &acc, ull a, ull b) {
    asm("fma.rn.f32x2 %0, %1, %2, %0;" : "+l"(acc) : "l"(a), "l"(b));
}
__device__ __forceinline__ ull dup2(float v) {
    unsigned int u = __float_as_uint(v);
    return ((ull)u << 32) | (ull)u;
}
__device__ __forceinline__ ull pack2(float x, float y) {
    return ((ull)__float_as_uint(y) << 32) | (ull)__float_as_uint(x);
}
__device__ __forceinline__ float2 unpack2(ull p) {
    float2 r;
    r.x = __uint_as_float((unsigned int)(p & 0xffffffffull));
    r.y = __uint_as_float((unsigned int)(p >> 32));
    return r;
}
// tanh via exp, saturates correctly at +-1
__device__ __forceinline__ float tanh_fast(float x) {
    float t = __expf(2.0f * x);
    return 1.0f - __fdividef(2.0f, t + 1.0f);
}

// ---------------- K0: fold weights ------------------------------------------
__global__ void prep_kernel(const float* __restrict__ Wf, const float* __restrict__ Wq,
                            const float* __restrict__ Wk, const float* __restrict__ Wa) {
    int d = blockIdx.x;      // 0..127
    int c = threadIdx.x;     // 0..127
    g_A[d*C + c] = Wf[d*C + c]        + Wf[(256+d)*C + c];
    g_B[d*C + c] = Wf[(128+d)*C + c]  - Wf[(256+d)*C + c];
    __shared__ float sWa[C], sWq[C];
    sWa[c] = Wa[c];
    sWq[c] = Wq[d*C + c];
    __syncthreads();
    float acc = 0.0f;
    #pragma unroll 4
    for (int k = 0; k < C; k++) acc += sWq[k] * sWa[k] * Wk[c*C + k];
    g_M[d*C + c] = acc * 0.08838834764831845f;   // 128^-0.5
}

// ---------------- zero accumulators ------------------------------------------
__global__ void zero_kernel() {
    int i = blockIdx.x * blockDim.x + threadIdx.x;
    if (i < NN*C) g_aggr[i] = 0.0f;
    if (i < NN)   g_asum[i] = 0.0f;
}

// ============ shared node-GEMM microkernel scheme =============================
#define NODE_SMEM (65536 + 128*33*8)

__device__ __forceinline__ void node_gemm_tile(const ull* sX2, const ulonglong2* sWu2,
                                               int lane, int nb, ull bi0, ull bi1,
                                               ull a0[4], ull a1[4]) {
    #pragma unroll
    for (int e = 0; e < 4; e++) { a0[e] = bi0; a1[e] = bi1; }
    #pragma unroll 8
    for (int d = 0; d < C; d++) {
        ulonglong2 wv = sWu2[d*32 + lane];
        #pragma unroll
        for (int e = 0; e < 4; e++) {
            ull xv = sX2[d*33 + nb + e];
            fma2(a0[e], xv, wv.x);
            fma2(a1[e], xv, wv.y);
        }
    }
}

// ---------------- K1: node precompute XA, XB, Xm -----------------------------
__global__ __launch_bounds__(256, 2) void node_pre_kernel(const float* __restrict__ x) {
    extern __shared__ unsigned char smem[];
    float4*     sW4  = (float4*)smem;
    ulonglong2* sWu2 = (ulonglong2*)smem;
    ull*        sX2  = (ull*)(smem + 65536);
    int tid = threadIdx.x, lane = tid & 31, w = tid >> 5;
    const float* Ws[3] = {g_A, g_B, g_M};
    float*       Ys[3] = {g_XA, g_XB, g_Xm};
    const int ntiles = (NN + 31) / 32;
    for (int m = 0; m < 3; m++) {
        __syncthreads();
        const float4* W4 = (const float4*)Ws[m];
        for (int i = tid; i < C*32; i += 256) sW4[i] = W4[i];
        float* Y = Ys[m];
        for (int tile = blockIdx.x; tile < ntiles; tile += gridDim.x) {
            int n0 = tile * 32;
            __syncthreads();
            for (int i = tid; i < C*32; i += 256) {
                int d = i & 127, n = i >> 7, ng = n0 + n;
                float v = (ng < NN) ? x[(size_t)ng*C + d] : 0.0f;
                sX2[d*33 + n] = dup2(v);
            }
            __syncthreads();
            int nb = w * 4;
            ull a0[4], a1[4];
            node_gemm_tile(sX2, sWu2, lane, nb, 0ull, 0ull, a0, a1);
            #pragma unroll 1
            for (int e = 0; e < 4; e++) {
                int n = n0 + nb + e;
                if (n < NN) {
                    float2 f0 = unpack2(a0[e]), f1 = unpack2(a1[e]);
                    float4 o; o.x = f0.x; o.y = f0.y; o.z = f1.x; o.w = f1.y;
                    *(float4*)(Y + (size_t)n*C + 4*lane) = o;
                }
            }
        }
    }
}

// ---------------- K2: edge pass — f, a, scatter exp(a)*f and a ----------------
// 256 thr (8 warps), 64 edges/tile, warp = 8 edges (4 edge-pairs) x 128 ch.
// smem layout (all wide regions 16B-aligned):
//   sW4  [65][32] float4  @ 0      33280 B
//   sEa2 [65][34] u64     @ 33280  17680 B  (u64 = edge-pair; stride 34 even ->
//                                            16B-aligned ulonglong2 pair reads)
//   sBf4 [32]  float4     @ 50960    512 B
//   sIdx [128] int        @ 51472    512 B
#define E1_SW   0
#define E1_SEA  33280
#define E1_SBF  50960
#define E1_SIDX 51472
#define E1_SMEM 51984

__global__ __launch_bounds__(256, 4) void edge1_kernel(const float* __restrict__ ea,
                                                       const int*   __restrict__ ei,
                                                       const float* __restrict__ Wf,
                                                       const float* __restrict__ bf) {
    extern __shared__ unsigned char smem[];
    float4*     sW4  = (float4*)(smem + E1_SW);
    ull*        sEa2 = (ull*)(smem + E1_SEA);
    float*      sEaF = (float*)(smem + E1_SEA);
    float4*     sBf4 = (float4*)(smem + E1_SBF);
    int*        sIdx = (int*)(smem + E1_SIDX);
    int tid = threadIdx.x, lane = tid & 31, w = tid >> 5;

    for (int i = tid; i < EF*32; i += 256) {
        int d = i >> 5, l = i & 31;
        sW4[i] = *(const float4*)(Wf + (size_t)(3*C + d)*C + 4*l);
    }
    if (tid < 32) sBf4[tid] = *(const float4*)(bf + 4*tid);
    __syncthreads();
    float4 b4 = sBf4[lane];
    ull bi0 = dup2(b4.x), bi1 = dup2(b4.y), bi2 = dup2(b4.z), bi3 = dup2(b4.w);

    const int eb = w * 8;                 // this warp's 8 edges within the tile
    const int pb = w * 4;                 // this warp's 4 edge-pairs
    const int ntiles = E / ET;            // 12500
    for (int tile = blockIdx.x; tile < ntiles; tile += gridDim.x) {
        int e0 = tile * ET;
        __syncthreads();
        if (tid < ET)           sIdx[tid] = ei[e0 + tid];
        else if (tid < 2*ET)    sIdx[tid] = ei[E + e0 + tid - ET];
        // coalesced ea staging, streaming (evict-first) loads keep L2 for gathers
        #pragma unroll 1
        for (int i = 0; i < 8; i++) {
            int e = eb + i, pr = e >> 1, par = e & 1;
            const float* row = ea + (size_t)(e0 + e)*EAC;
            float2 v = __ldcs((const float2*)(row + 2*lane));
            sEaF[(2*lane)*68   + 2*pr + par] = v.x;
            sEaF[(2*lane+1)*68 + 2*pr + par] = v.y;
            if (lane == 0) sEaF[64*68 + 2*pr + par] = __ldcs(row + 64);
        }
        __syncthreads();

        // GEMM: acc[c][p] = f32x2 accumulator for channel 4*lane+c, edge pair p
        ull a0[4], a1[4], a2[4], a3[4];
        #pragma unroll
        for (int p = 0; p < 4; p++) { a0[p]=bi0; a1[p]=bi1; a2[p]=bi2; a3[p]=bi3; }
        #pragma unroll 5
        for (int d = 0; d < EF; d++) {
            float4 wv = sW4[d*32 + lane];
            ull w0 = dup2(wv.x), w1 = dup2(wv.y), w2 = dup2(wv.z), w3 = dup2(wv.w);
            const ulonglong2* er2 = (const ulonglong2*)(sEa2 + d*34 + pb);
            ulonglong2 ep01 = er2[0];      // pairs p=0,1 (uniform LDS.128 bcast)
            ulonglong2 ep23 = er2[1];      // pairs p=2,3
            ull ep[4] = {ep01.x, ep01.y, ep23.x, ep23.y};
            #pragma unroll
            for (int p = 0; p < 4; p++) {
                fma2(a0[p], ep[p], w0);
                fma2(a1[p], ep[p], w1);
                fma2(a2[p], ep[p], w2);
                fma2(a3[p], ep[p], w3);
            }
        }
        #pragma unroll 1
        for (int p = 0; p < 4; p++) {
            float2 c0 = unpack2(a0[p]), c1 = unpack2(a1[p]);
            float2 c2 = unpack2(a2[p]), c3 = unpack2(a3[p]);
            #pragma unroll
            for (int par = 0; par < 2; par++) {
                int e  = eb + 2*p + par;
                int s = sIdx[e], t = sIdx[ET + e];
                float v0 = par ? c0.y : c0.x;
                float v1 = par ? c1.y : c1.x;
                float v2 = par ? c2.y : c2.x;
                float v3 = par ? c3.y : c3.x;
                float4 xa = __ldg((const float4*)(g_XA + (size_t)s*C + 4*lane));
                float4 xb = __ldg((const float4*)(g_XB + (size_t)t*C + 4*lane));
                float4 xm = __ldg((const float4*)(g_Xm + (size_t)s*C + 4*lane));
                v0 += xa.x + xb.x;
                v1 += xa.y + xb.y;
                v2 += xa.z + xb.z;
                v3 += xa.w + xb.w;
                v0 = v0 > 0.0f ? v0 : __expf(v0) - 1.0f;
                v1 = v1 > 0.0f ? v1 : __expf(v1) - 1.0f;
                v2 = v2 > 0.0f ? v2 : __expf(v2) - 1.0f;
                v3 = v3 > 0.0f ? v3 : __expf(v3) - 1.0f;
                float msk = (sEaF[2*(pb + p) + par] < 8.0f) ? 1.0f : 0.0f;
                v0 *= msk; v1 *= msk; v2 *= msk; v3 *= msk;
                float pd = v0*xm.x + v1*xm.y + v2*xm.z + v3*xm.w;
                #pragma unroll
                for (int off = 16; off; off >>= 1)
                    pd += __shfl_xor_sync(0xffffffffu, pd, off);
                float av = tanh_fast(pd);
                float sc = __expf(av);
                asm volatile("red.global.add.v4.f32 [%0], {%1, %2, %3, %4};"
                             :: "l"(g_aggr + (size_t)s*C + 4*lane),
                                "f"(sc*v0), "f"(sc*v1), "f"(sc*v2), "f"(sc*v3)
                             : "memory");
                if (lane == 0) atomicAdd(&g_asum[s], av);
            }
        }
    }
}

// ---------------- K4: out = (x + exp(-asum)*aggr) @ Wu + bu ------------------
__global__ __launch_bounds__(256, 2) void node_out_kernel(const float* __restrict__ x,
                                                          const float* __restrict__ Wu,
                                                          const float* __restrict__ bu,
                                                          float* __restrict__ out) {
    extern __shared__ unsigned char smem[];
    float4*     sW4  = (float4*)smem;
    ulonglong2* sWu2 = (ulonglong2*)smem;
    ull*        sX2  = (ull*)(smem + 65536);
    int tid = threadIdx.x, lane = tid & 31, w = tid >> 5;
    const float4* W4 = (const float4*)Wu;
    for (int i = tid; i < C*32; i += 256) sW4[i] = W4[i];
    float4 b4 = *(const float4*)(bu + 4*lane);
    ull bi0 = pack2(b4.x, b4.y), bi1 = pack2(b4.z, b4.w);
    const int ntiles = (NN + 31) / 32;
    for (int tile = blockIdx.x; tile < ntiles; tile += gridDim.x) {
        int n0 = tile * 32;
        __syncthreads();
        for (int i = tid; i < C*32; i += 256) {
            int d = i & 127, n = i >> 7, ng = n0 + n;
            float v = 0.0f;
            if (ng < NN) {
                float dsc = __expf(-g_asum[ng]);
                v = x[(size_t)ng*C + d] + dsc * g_aggr[(size_t)ng*C + d];
            }
            sX2[d*33 + n] = dup2(v);
        }
        __syncthreads();
        int nb = w * 4;
        ull a0[4], a1[4];
        node_gemm_tile(sX2, sWu2, lane, nb, bi0, bi1, a0, a1);
        #pragma unroll 1
        for (int e = 0; e < 4; e++) {
            int n = n0 + nb + e;
            if (n < NN) {
                float2 f0 = unpack2(a0[e]), f1 = unpack2(a1[e]);
                float4 o; o.x = f0.x; o.y = f0.y; o.z = f1.x; o.w = f1.y;
                *(float4*)(out + (size_t)n*C + 4*lane) = o;
            }
        }
    }
}

// ---------------- host launcher ----------------------------------------------
extern "C" void kernel_launch(void* const* d_in, const int* in_sizes, int n_in,
                              void* d_out, int out_size) {
    const float* x   = (const float*)d_in[0];
    const int*   ei  = (const int*  )d_in[1];
    const float* ea  = (const float*)d_in[2];
    const float* Wf  = (const float*)d_in[3];
    const float* bf  = (const float*)d_in[4];
    const float* Wq  = (const float*)d_in[5];
    const float* Wk  = (const float*)d_in[6];
    const float* Wa  = (const float*)d_in[7];
    const float* Wu  = (const float*)d_in[8];
    const float* bu  = (const float*)d_in[9];
    float* out = (float*)d_out;

    (void)in_sizes; (void)n_in; (void)out_size;

    cudaFuncSetAttribute(node_pre_kernel, cudaFuncAttributeMaxDynamicSharedMemorySize, NODE_SMEM);
    cudaFuncSetAttribute(node_out_kernel, cudaFuncAttributeMaxDynamicSharedMemorySize, NODE_SMEM);
    cudaFuncSetAttribute(edge1_kernel,    cudaFuncAttributeMaxDynamicSharedMemorySize, E1_SMEM);

    prep_kernel<<<C, C>>>(Wf, Wq, Wk, Wa);
    zero_kernel<<<(NN*C + 255) / 256, 256>>>();
    node_pre_kernel<<<296, 256, NODE_SMEM>>>(x);
    edge1_kernel<<<592, 256, E1_SMEM>>>(ea, ei, Wf, bf);
    node_out_kernel<<<296, 256, NODE_SMEM>>>(x, Wu, bu, out);
}

// round 9
// speedup vs baseline: 1.0134x; 1.0134x over previous
#include <cuda_runtime.h>

#define NN   50000
#define C    128
#define E    800000
#define EF   65
#define EAC  70
#define ET   64

typedef unsigned long long ull;

// ---------------- scratch (device globals; no allocation allowed) ------------
__device__ float g_A [C*C];           // Wf1 + Wf3
__device__ float g_B [C*C];           // Wf2 - Wf3
__device__ float g_M [C*C];           // scale * Wq diag(Wa) Wk^T
__device__ float g_XA[NN*C];          // x @ A
__device__ float g_XB[NN*C];          // x @ B
__device__ float g_Xm[NN*C];          // x @ M
__device__ float g_asum[NN];          // segment sum of a over src
__device__ float g_aggr[NN*C];        // segment sum of exp(a)*f over src

// ---------------- packed fp32x2 helpers (Blackwell FFMA2) --------------------
__device__ __forceinline__ void fma2(ull &acc, ull a, ull b) {
    asm("fma.rn.f32x2 %0, %1, %2, %0;" : "+l"(acc) : "l"(a), "l"(b));
}
__device__ __forceinline__ ull dup2(float v) {
    unsigned int u = __float_as_uint(v);
    return ((ull)u << 32) | (ull)u;
}
__device__ __forceinline__ ull pack2(float x, float y) {
    return ((ull)__float_as_uint(y) << 32) | (ull)__float_as_uint(x);
}
__device__ __forceinline__ float2 unpack2(ull p) {
    float2 r;
    r.x = __uint_as_float((unsigned int)(p & 0xffffffffull));
    r.y = __uint_as_float((unsigned int)(p >> 32));
    return r;
}
// tanh via exp, saturates correctly at +-1
__device__ __forceinline__ float tanh_fast(float x) {
    float t = __expf(2.0f * x);
    return 1.0f - __fdividef(2.0f, t + 1.0f);
}

// ---------------- K0: fold weights ------------------------------------------
__global__ void prep_kernel(const float* __restrict__ Wf, const float* __restrict__ Wq,
                            const float* __restrict__ Wk, const float* __restrict__ Wa) {
    int d = blockIdx.x;      // 0..127
    int c = threadIdx.x;     // 0..127
    g_A[d*C + c] = Wf[d*C + c]        + Wf[(256+d)*C + c];
    g_B[d*C + c] = Wf[(128+d)*C + c]  - Wf[(256+d)*C + c];
    __shared__ float sWa[C], sWq[C];
    sWa[c] = Wa[c];
    sWq[c] = Wq[d*C + c];
    __syncthreads();
    float acc = 0.0f;
    #pragma unroll 4
    for (int k = 0; k < C; k++) acc += sWq[k] * sWa[k] * Wk[c*C + k];
    g_M[d*C + c] = acc * 0.08838834764831845f;   // 128^-0.5
}

// ---------------- zero accumulators ------------------------------------------
__global__ void zero_kernel() {
    int i = blockIdx.x * blockDim.x + threadIdx.x;
    if (i < NN*C) g_aggr[i] = 0.0f;
    if (i < NN)   g_asum[i] = 0.0f;
}

// ============ shared node-GEMM microkernel scheme =============================
#define NODE_SMEM (65536 + 128*33*8)

__device__ __forceinline__ void node_gemm_tile(const ull* sX2, const ulonglong2* sWu2,
                                               int lane, int nb, ull bi0, ull bi1,
                                               ull a0[4], ull a1[4]) {
    #pragma unroll
    for (int e = 0; e < 4; e++) { a0[e] = bi0; a1[e] = bi1; }
    #pragma unroll 8
    for (int d = 0; d < C; d++) {
        ulonglong2 wv = sWu2[d*32 + lane];
        #pragma unroll
        for (int e = 0; e < 4; e++) {
            ull xv = sX2[d*33 + nb + e];
            fma2(a0[e], xv, wv.x);
            fma2(a1[e], xv, wv.y);
        }
    }
}

// ---------------- K1: node precompute XA, XB, Xm -----------------------------
__global__ __launch_bounds__(256, 2) void node_pre_kernel(const float* __restrict__ x) {
    extern __shared__ unsigned char smem[];
    float4*     sW4  = (float4*)smem;
    ulonglong2* sWu2 = (ulonglong2*)smem;
    ull*        sX2  = (ull*)(smem + 65536);
    int tid = threadIdx.x, lane = tid & 31, w = tid >> 5;
    const float* Ws[3] = {g_A, g_B, g_M};
    float*       Ys[3] = {g_XA, g_XB, g_Xm};
    const int ntiles = (NN + 31) / 32;
    for (int m = 0; m < 3; m++) {
        __syncthreads();
        const float4* W4 = (const float4*)Ws[m];
        for (int i = tid; i < C*32; i += 256) sW4[i] = W4[i];
        float* Y = Ys[m];
        for (int tile = blockIdx.x; tile < ntiles; tile += gridDim.x) {
            int n0 = tile * 32;
            __syncthreads();
            for (int i = tid; i < C*32; i += 256) {
                int d = i & 127, n = i >> 7, ng = n0 + n;
                float v = (ng < NN) ? x[(size_t)ng*C + d] : 0.0f;
                sX2[d*33 + n] = dup2(v);
            }
            __syncthreads();
            int nb = w * 4;
            ull a0[4], a1[4];
            node_gemm_tile(sX2, sWu2, lane, nb, 0ull, 0ull, a0, a1);
            #pragma unroll 1
            for (int e = 0; e < 4; e++) {
                int n = n0 + nb + e;
                if (n < NN) {
                    float2 f0 = unpack2(a0[e]), f1 = unpack2(a1[e]);
                    float4 o; o.x = f0.x; o.y = f0.y; o.z = f1.x; o.w = f1.y;
                    *(float4*)(Y + (size_t)n*C + 4*lane) = o;
                }
            }
        }
    }
}

// ---------------- K2: edge pass — f, a, scatter exp(a)*f and a ----------------
// 256 thr (8 warps), 64 edges/tile, warp = 8 edges (4 edge-pairs) x 128 ch.
// smem layout (R6-proven; all wide regions aligned):
//   sW4  [65][32] float4  @ 0      33280 B
//   sEa  [65][66] float   @ 33280  17160 B  (row stride 66 fl = 33 u64;
//                                            u64 col p = edge pair {2p,2p+1})
//   sBf4 [32]  float4     @ 50448    512 B
//   sIdx [128] int        @ 50960    512 B
#define E1_SW   0
#define E1_SEA  33280
#define E1_SBF  50448
#define E1_SIDX 50960
#define E1_SMEM 51472

__global__ __launch_bounds__(256, 4) void edge1_kernel(const float* __restrict__ ea,
                                                       const int*   __restrict__ ei,
                                                       const float* __restrict__ Wf,
                                                       const float* __restrict__ bf) {
    extern __shared__ unsigned char smem[];
    float4*     sW4  = (float4*)(smem + E1_SW);
    ull*        sEa2 = (ull*)(smem + E1_SEA);
    float*      sEaF = (float*)(smem + E1_SEA);
    float4*     sBf4 = (float4*)(smem + E1_SBF);
    int*        sIdx = (int*)(smem + E1_SIDX);
    int tid = threadIdx.x, lane = tid & 31, w = tid >> 5;

    for (int i = tid; i < EF*32; i += 256) {
        int d = i >> 5, l = i & 31;
        sW4[i] = *(const float4*)(Wf + (size_t)(3*C + d)*C + 4*l);
    }
    if (tid < 32) sBf4[tid] = *(const float4*)(bf + 4*tid);
    __syncthreads();
    float4 b4 = sBf4[lane];
    ull bi0 = dup2(b4.x), bi1 = dup2(b4.y), bi2 = dup2(b4.z), bi3 = dup2(b4.w);

    const int eb = w * 8;                 // this warp's 8 edges within the tile
    const int pb = w * 4;                 // this warp's 4 edge-pairs
    const int ntiles = E / ET;            // 12500
    for (int tile = blockIdx.x; tile < ntiles; tile += gridDim.x) {
        int e0 = tile * ET;
        __syncthreads();
        if (tid < ET)           sIdx[tid] = ei[e0 + tid];
        else if (tid < 2*ET)    sIdx[tid] = ei[E + e0 + tid - ET];
        // coalesced ea staging, streaming (evict-first) loads keep L2 for gathers
        #pragma unroll 1
        for (int i = 0; i < 8; i++) {
            int e = eb + i;
            const float* row = ea + (size_t)(e0 + e)*EAC;
            float2 v = __ldcs((const float2*)(row + 2*lane));
            sEaF[(2*lane)*66   + e] = v.x;
            sEaF[(2*lane+1)*66 + e] = v.y;
            if (lane == 0) sEaF[64*66 + e] = __ldcs(row + 64);
        }
        __syncthreads();

        // GEMM: acc[c][p] = f32x2 accumulator for channel 4*lane+c, edge pair p
        ull a0[4], a1[4], a2[4], a3[4];
        #pragma unroll
        for (int p = 0; p < 4; p++) { a0[p]=bi0; a1[p]=bi1; a2[p]=bi2; a3[p]=bi3; }
        #pragma unroll 5
        for (int d = 0; d < EF; d++) {
            float4 wv = sW4[d*32 + lane];
            ull w0 = dup2(wv.x), w1 = dup2(wv.y), w2 = dup2(wv.z), w3 = dup2(wv.w);
            const ull* er = sEa2 + d*33 + pb;
            #pragma unroll
            for (int p = 0; p < 4; p++) {
                ull ep = er[p];                  // LDS.64 broadcast
                fma2(a0[p], ep, w0);
                fma2(a1[p], ep, w1);
                fma2(a2[p], ep, w2);
                fma2(a3[p], ep, w3);
            }
        }

        // ---- pipelined epilogue: prefetch edge i+1's gathers during edge i ----
        int sCur = sIdx[eb], tCur = sIdx[ET + eb];
        float4 xa = __ldg((const float4*)(g_XA + (size_t)sCur*C + 4*lane));
        float4 xb = __ldg((const float4*)(g_XB + (size_t)tCur*C + 4*lane));
        float4 xm = __ldg((const float4*)(g_Xm + (size_t)sCur*C + 4*lane));
        #pragma unroll
        for (int i = 0; i < 8; i++) {
            const int p = i >> 1, par = i & 1;
            float4 cxa = xa, cxb = xb, cxm = xm;
            int s = sCur;
            if (i < 7) {
                int sN = sIdx[eb + i + 1], tN = sIdx[ET + eb + i + 1];
                xa = __ldg((const float4*)(g_XA + (size_t)sN*C + 4*lane));
                xb = __ldg((const float4*)(g_XB + (size_t)tN*C + 4*lane));
                xm = __ldg((const float4*)(g_Xm + (size_t)sN*C + 4*lane));
                sCur = sN; tCur = tN;
            }
            float2 c0 = unpack2(a0[p]), c1 = unpack2(a1[p]);
            float2 c2 = unpack2(a2[p]), c3 = unpack2(a3[p]);
            float v0 = (par ? c0.y : c0.x) + cxa.x + cxb.x;
            float v1 = (par ? c1.y : c1.x) + cxa.y + cxb.y;
            float v2 = (par ? c2.y : c2.x) + cxa.z + cxb.z;
            float v3 = (par ? c3.y : c3.x) + cxa.w + cxb.w;
            v0 = v0 > 0.0f ? v0 : __expf(v0) - 1.0f;
            v1 = v1 > 0.0f ? v1 : __expf(v1) - 1.0f;
            v2 = v2 > 0.0f ? v2 : __expf(v2) - 1.0f;
            v3 = v3 > 0.0f ? v3 : __expf(v3) - 1.0f;
            float msk = (sEaF[eb + i] < 8.0f) ? 1.0f : 0.0f;
            v0 *= msk; v1 *= msk; v2 *= msk; v3 *= msk;
            float pd = v0*cxm.x + v1*cxm.y + v2*cxm.z + v3*cxm.w;
            #pragma unroll
            for (int off = 16; off; off >>= 1)
                pd += __shfl_xor_sync(0xffffffffu, pd, off);
            float av = tanh_fast(pd);
            float sc = __expf(av);
            asm volatile("red.global.add.v4.f32 [%0], {%1, %2, %3, %4};"
                         :: "l"(g_aggr + (size_t)s*C + 4*lane),
                            "f"(sc*v0), "f"(sc*v1), "f"(sc*v2), "f"(sc*v3)
                         : "memory");
            if (lane == 0) atomicAdd(&g_asum[s], av);
        }
    }
}

// ---------------- K4: out = (x + exp(-asum)*aggr) @ Wu + bu ------------------
__global__ __launch_bounds__(256, 2) void node_out_kernel(const float* __restrict__ x,
                                                          const float* __restrict__ Wu,
                                                          const float* __restrict__ bu,
                                                          float* __restrict__ out) {
    extern __shared__ unsigned char smem[];
    float4*     sW4  = (float4*)smem;
    ulonglong2* sWu2 = (ulonglong2*)smem;
    ull*        sX2  = (ull*)(smem + 65536);
    int tid = threadIdx.x, lane = tid & 31, w = tid >> 5;
    const float4* W4 = (const float4*)Wu;
    for (int i = tid; i < C*32; i += 256) sW4[i] = W4[i];
    float4 b4 = *(const float4*)(bu + 4*lane);
    ull bi0 = pack2(b4.x, b4.y), bi1 = pack2(b4.z, b4.w);
    const int ntiles = (NN + 31) / 32;
    for (int tile = blockIdx.x; tile < ntiles; tile += gridDim.x) {
        int n0 = tile * 32;
        __syncthreads();
        for (int i = tid; i < C*32; i += 256) {
            int d = i & 127, n = i >> 7, ng = n0 + n;
            float v = 0.0f;
            if (ng < NN) {
                float dsc = __expf(-g_asum[ng]);
                v = x[(size_t)ng*C + d] + dsc * g_aggr[(size_t)ng*C + d];
            }
            sX2[d*33 + n] = dup2(v);
        }
        __syncthreads();
        int nb = w * 4;
        ull a0[4], a1[4];
        node_gemm_tile(sX2, sWu2, lane, nb, bi0, bi1, a0, a1);
        #pragma unroll 1
        for (int e = 0; e < 4; e++) {
            int n = n0 + nb + e;
            if (n < NN) {
                float2 f0 = unpack2(a0[e]), f1 = unpack2(a1[e]);
                float4 o; o.x = f0.x; o.y = f0.y; o.z = f1.x; o.w = f1.y;
                *(float4*)(out + (size_t)n*C + 4*lane) = o;
            }
        }
    }
}

// ---------------- host launcher ----------------------------------------------
extern "C" void kernel_launch(void* const* d_in, const int* in_sizes, int n_in,
                              void* d_out, int out_size) {
    const float* x   = (const float*)d_in[0];
    const int*   ei  = (const int*  )d_in[1];
    const float* ea  = (const float*)d_in[2];
    const float* Wf  = (const float*)d_in[3];
    const float* bf  = (const float*)d_in[4];
    const float* Wq  = (const float*)d_in[5];
    const float* Wk  = (const float*)d_in[6];
    const float* Wa  = (const float*)d_in[7];
    const float* Wu  = (const float*)d_in[8];
    const float* bu  = (const float*)d_in[9];
    float* out = (float*)d_out;

    (void)in_sizes; (void)n_in; (void)out_size;

    cudaFuncSetAttribute(node_pre_kernel, cudaFuncAttributeMaxDynamicSharedMemorySize, NODE_SMEM);
    cudaFuncSetAttribute(node_out_kernel, cudaFuncAttributeMaxDynamicSharedMemorySize, NODE_SMEM);
    cudaFuncSetAttribute(edge1_kernel,    cudaFuncAttributeMaxDynamicSharedMemorySize, E1_SMEM);

    prep_kernel<<<C, C>>>(Wf, Wq, Wk, Wa);
    zero_kernel<<<(NN*C + 255) / 256, 256>>>();
    node_pre_kernel<<<296, 256, NODE_SMEM>>>(x);
    edge1_kernel<<<592, 256, E1_SMEM>>>(ea, ei, Wf, bf);
    node_out_kernel<<<296, 256, NODE_SMEM>>>(x, Wu, bu, out);
}

// round 10
// speedup vs baseline: 1.0931x; 1.0787x over previous
#include <cuda_runtime.h>

#define NN   50000
#define C    128
#define E    800000
#define EF   65
#define EAC  70
#define ET   64

typedef unsigned long long ull;

// ---------------- scratch (device globals; no allocation allowed) ------------
__device__ float g_A [C*C];           // Wf1 + Wf3
__device__ float g_B [C*C];           // Wf2 - Wf3
__device__ float g_M [C*C];           // scale * Wq diag(Wa) Wk^T
__device__ float g_XA[NN*C];          // x @ A
__device__ float g_XB[NN*C];          // x @ B
__device__ float g_Xm[NN*C];          // x @ M
__device__ float g_asum[NN];          // segment sum of a over src
__device__ float g_aggr[NN*C];        // segment sum of exp(a)*f over src

// ---------------- packed fp32x2 helpers (Blackwell FFMA2) --------------------
__device__ __forceinline__ void fma2(ull &acc, ull a, ull b) {
    asm("fma.rn.f32x2 %0, %1, %2, %0;" : "+l"(acc) : "l"(a), "l"(b));
}
__device__ __forceinline__ ull dup2(float v) {
    unsigned int u = __float_as_uint(v);
    return ((ull)u << 32) | (ull)u;
}
__device__ __forceinline__ ull pack2(float x, float y) {
    return ((ull)__float_as_uint(y) << 32) | (ull)__float_as_uint(x);
}
__device__ __forceinline__ float2 unpack2(ull p) {
    float2 r;
    r.x = __uint_as_float((unsigned int)(p & 0xffffffffull));
    r.y = __uint_as_float((unsigned int)(p >> 32));
    return r;
}
// tanh via exp, saturates correctly at +-1
__device__ __forceinline__ float tanh_fast(float x) {
    float t = __expf(2.0f * x);
    return 1.0f - __fdividef(2.0f, t + 1.0f);
}

// ---------------- K0: fold weights ------------------------------------------
__global__ void prep_kernel(const float* __restrict__ Wf, const float* __restrict__ Wq,
                            const float* __restrict__ Wk, const float* __restrict__ Wa) {
    int d = blockIdx.x;      // 0..127
    int c = threadIdx.x;     // 0..127
    g_A[d*C + c] = Wf[d*C + c]        + Wf[(256+d)*C + c];
    g_B[d*C + c] = Wf[(128+d)*C + c]  - Wf[(256+d)*C + c];
    __shared__ float sWa[C], sWq[C];
    sWa[c] = Wa[c];
    sWq[c] = Wq[d*C + c];
    __syncthreads();
    float acc = 0.0f;
    #pragma unroll 4
    for (int k = 0; k < C; k++) acc += sWq[k] * sWa[k] * Wk[c*C + k];
    g_M[d*C + c] = acc * 0.08838834764831845f;   // 128^-0.5
}

// ---------------- zero accumulators ------------------------------------------
__global__ void zero_kernel() {
    int i = blockIdx.x * blockDim.x + threadIdx.x;
    if (i < NN*C) g_aggr[i] = 0.0f;
    if (i < NN)   g_asum[i] = 0.0f;
}

// ============ K-split node-GEMM scheme ========================================
// 256 thr (8 warps), 32-node tile, warp = 4 nodes x 128 ch, K processed in two
// 64-row halves so only half the weights (32 KB) + f32 x-half (8.4 KB) live in
// smem -> 4 blocks/SM (reg-capped), 50% occ. Partial sums accumulate in Y.
//   sW4 [64][32] float4 @ 0      32768 B
//   sXf [64][33] f32    @ 32768   8448 B
#define NODE_SW   0
#define NODE_SX   32768
#define NODE_SMEM 41216

// one K-half GEMM over a staged tile; accums in/out
__device__ __forceinline__ void node_gemm_half(const float* sXf, const ulonglong2* sWu2,
                                               int lane, int nb, ull a0[4], ull a1[4]) {
    #pragma unroll 8
    for (int d = 0; d < 64; d++) {
        ulonglong2 wv = sWu2[d*32 + lane];
        #pragma unroll
        for (int e = 0; e < 4; e++) {
            ull xv = dup2(sXf[d*33 + nb + e]);
            fma2(a0[e], xv, wv.x);
            fma2(a1[e], xv, wv.y);
        }
    }
}

// ---------------- K1: node precompute XA, XB, Xm -----------------------------
__global__ __launch_bounds__(256, 4) void node_pre_kernel(const float* __restrict__ x) {
    extern __shared__ unsigned char smem[];
    float4*     sW4  = (float4*)(smem + NODE_SW);
    ulonglong2* sWu2 = (ulonglong2*)(smem + NODE_SW);
    float*      sXf  = (float*)(smem + NODE_SX);
    int tid = threadIdx.x, lane = tid & 31, w = tid >> 5;
    const float* Ws[3] = {g_A, g_B, g_M};
    float*       Ys[3] = {g_XA, g_XB, g_Xm};
    const int ntiles = (NN + 31) / 32;
    for (int m = 0; m < 3; m++) {
        const float4* W4 = (const float4*)Ws[m];
        float* Y = Ys[m];
        for (int h = 0; h < 2; h++) {
            __syncthreads();
            for (int i = tid; i < 64*32; i += 256) {
                int dd = i >> 5, l = i & 31;
                sW4[i] = W4[(h*64 + dd)*32 + l];
            }
            for (int tile = blockIdx.x; tile < ntiles; tile += gridDim.x) {
                int n0 = tile * 32;
                __syncthreads();
                for (int i = tid; i < 64*32; i += 256) {
                    int d = i & 63, n = i >> 6, ng = n0 + n;
                    sXf[d*33 + n] = (ng < NN) ? x[(size_t)ng*C + h*64 + d] : 0.0f;
                }
                __syncthreads();
                int nb = w * 4;
                ull a0[4] = {0,0,0,0}, a1[4] = {0,0,0,0};
                node_gemm_half(sXf, sWu2, lane, nb, a0, a1);
                #pragma unroll 1
                for (int e = 0; e < 4; e++) {
                    int n = n0 + nb + e;
                    if (n < NN) {
                        float2 f0 = unpack2(a0[e]), f1 = unpack2(a1[e]);
                        float4 o; o.x = f0.x; o.y = f0.y; o.z = f1.x; o.w = f1.y;
                        float* yp = Y + (size_t)n*C + 4*lane;
                        if (h) {
                            float4 prev = *(float4*)yp;
                            o.x += prev.x; o.y += prev.y; o.z += prev.z; o.w += prev.w;
                        }
                        *(float4*)yp = o;
                    }
                }
            }
        }
    }
}

// ---------------- K2: edge pass — f, a, scatter exp(a)*f and a ----------------
// 256 thr (8 warps), 64 edges/tile, warp = 8 edges (4 edge-pairs) x 128 ch.
//   sW4  [65][32] float4  @ 0      33280 B
//   sEa  [65][66] float   @ 33280  17160 B  (u64 col p = edge pair {2p,2p+1})
//   sBf4 [32]  float4     @ 50448    512 B
//   sIdx [128] int        @ 50960    512 B
#define E1_SW   0
#define E1_SEA  33280
#define E1_SBF  50448
#define E1_SIDX 50960
#define E1_SMEM 51472

__global__ __launch_bounds__(256, 4) void edge1_kernel(const float* __restrict__ ea,
                                                       const int*   __restrict__ ei,
                                                       const float* __restrict__ Wf,
                                                       const float* __restrict__ bf) {
    extern __shared__ unsigned char smem[];
    float4*     sW4  = (float4*)(smem + E1_SW);
    ull*        sEa2 = (ull*)(smem + E1_SEA);
    float*      sEaF = (float*)(smem + E1_SEA);
    float4*     sBf4 = (float4*)(smem + E1_SBF);
    int*        sIdx = (int*)(smem + E1_SIDX);
    int tid = threadIdx.x, lane = tid & 31, w = tid >> 5;

    for (int i = tid; i < EF*32; i += 256) {
        int d = i >> 5, l = i & 31;
        sW4[i] = *(const float4*)(Wf + (size_t)(3*C + d)*C + 4*l);
    }
    if (tid < 32) sBf4[tid] = *(const float4*)(bf + 4*tid);
    __syncthreads();
    float4 b4 = sBf4[lane];
    ull bi0 = dup2(b4.x), bi1 = dup2(b4.y), bi2 = dup2(b4.z), bi3 = dup2(b4.w);

    const int eb = w * 8;                 // this warp's 8 edges within the tile
    const int pb = w * 4;                 // this warp's 4 edge-pairs
    const int ntiles = E / ET;            // 12500
    for (int tile = blockIdx.x; tile < ntiles; tile += gridDim.x) {
        int e0 = tile * ET;
        __syncthreads();
        if (tid < ET)           sIdx[tid] = ei[e0 + tid];
        else if (tid < 2*ET)    sIdx[tid] = ei[E + e0 + tid - ET];
        // coalesced ea staging, streaming (evict-first) loads keep L2 for gathers
        #pragma unroll 1
        for (int i = 0; i < 8; i++) {
            int e = eb + i;
            const float* row = ea + (size_t)(e0 + e)*EAC;
            float2 v = __ldcs((const float2*)(row + 2*lane));
            sEaF[(2*lane)*66   + e] = v.x;
            sEaF[(2*lane+1)*66 + e] = v.y;
            if (lane == 0) sEaF[64*66 + e] = __ldcs(row + 64);
        }
        __syncthreads();

        // GEMM: acc[c][p] = f32x2 accumulator for channel 4*lane+c, edge pair p
        ull a0[4], a1[4], a2[4], a3[4];
        #pragma unroll
        for (int p = 0; p < 4; p++) { a0[p]=bi0; a1[p]=bi1; a2[p]=bi2; a3[p]=bi3; }
        #pragma unroll 5
        for (int d = 0; d < EF; d++) {
            float4 wv = sW4[d*32 + lane];
            ull w0 = dup2(wv.x), w1 = dup2(wv.y), w2 = dup2(wv.z), w3 = dup2(wv.w);
            const ull* er = sEa2 + d*33 + pb;
            #pragma unroll
            for (int p = 0; p < 4; p++) {
                ull ep = er[p];                  // LDS.64 broadcast
                fma2(a0[p], ep, w0);
                fma2(a1[p], ep, w1);
                fma2(a2[p], ep, w2);
                fma2(a3[p], ep, w3);
            }
        }

        // ---- pipelined epilogue: prefetch edge i+1's gathers during edge i ----
        int sCur = sIdx[eb], tCur = sIdx[ET + eb];
        float4 xa = __ldg((const float4*)(g_XA + (size_t)sCur*C + 4*lane));
        float4 xb = __ldg((const float4*)(g_XB + (size_t)tCur*C + 4*lane));
        float4 xm = __ldg((const float4*)(g_Xm + (size_t)sCur*C + 4*lane));
        #pragma unroll
        for (int i = 0; i < 8; i++) {
            const int p = i >> 1, par = i & 1;
            float4 cxa = xa, cxb = xb, cxm = xm;
            int s = sCur;
            if (i < 7) {
                int sN = sIdx[eb + i + 1], tN = sIdx[ET + eb + i + 1];
                xa = __ldg((const float4*)(g_XA + (size_t)sN*C + 4*lane));
                xb = __ldg((const float4*)(g_XB + (size_t)tN*C + 4*lane));
                xm = __ldg((const float4*)(g_Xm + (size_t)sN*C + 4*lane));
                sCur = sN; tCur = tN;
            }
            float2 c0 = unpack2(a0[p]), c1 = unpack2(a1[p]);
            float2 c2 = unpack2(a2[p]), c3 = unpack2(a3[p]);
            float v0 = (par ? c0.y : c0.x) + cxa.x + cxb.x;
            float v1 = (par ? c1.y : c1.x) + cxa.y + cxb.y;
            float v2 = (par ? c2.y : c2.x) + cxa.z + cxb.z;
            float v3 = (par ? c3.y : c3.x) + cxa.w + cxb.w;
            v0 = v0 > 0.0f ? v0 : __expf(v0) - 1.0f;
            v1 = v1 > 0.0f ? v1 : __expf(v1) - 1.0f;
            v2 = v2 > 0.0f ? v2 : __expf(v2) - 1.0f;
            v3 = v3 > 0.0f ? v3 : __expf(v3) - 1.0f;
            float msk = (sEaF[eb + i] < 8.0f) ? 1.0f : 0.0f;
            v0 *= msk; v1 *= msk; v2 *= msk; v3 *= msk;
            float pd = v0*cxm.x + v1*cxm.y + v2*cxm.z + v3*cxm.w;
            #pragma unroll
            for (int off = 16; off; off >>= 1)
                pd += __shfl_xor_sync(0xffffffffu, pd, off);
            float av = tanh_fast(pd);
            float sc = __expf(av);
            asm volatile("red.global.add.v4.f32 [%0], {%1, %2, %3, %4};"
                         :: "l"(g_aggr + (size_t)s*C + 4*lane),
                            "f"(sc*v0), "f"(sc*v1), "f"(sc*v2), "f"(sc*v3)
                         : "memory");
            if (lane == 0) atomicAdd(&g_asum[s], av);
        }
    }
}

// ---------------- K4: out = (x + exp(-asum)*aggr) @ Wu + bu ------------------
__global__ __launch_bounds__(256, 4) void node_out_kernel(const float* __restrict__ x,
                                                          const float* __restrict__ Wu,
                                                          const float* __restrict__ bu,
                                                          float* __restrict__ out) {
    extern __shared__ unsigned char smem[];
    float4*     sW4  = (float4*)(smem + NODE_SW);
    ulonglong2* sWu2 = (ulonglong2*)(smem + NODE_SW);
    float*      sXf  = (float*)(smem + NODE_SX);
    int tid = threadIdx.x, lane = tid & 31, w = tid >> 5;
    const float4* W4 = (const float4*)Wu;
    float4 b4 = *(const float4*)(bu + 4*lane);
    ull bi0 = pack2(b4.x, b4.y), bi1 = pack2(b4.z, b4.w);
    const int ntiles = (NN + 31) / 32;
    for (int h = 0; h < 2; h++) {
        __syncthreads();
        for (int i = tid; i < 64*32; i += 256) {
            int dd = i >> 5, l = i & 31;
            sW4[i] = W4[(h*64 + dd)*32 + l];
        }
        for (int tile = blockIdx.x; tile < ntiles; tile += gridDim.x) {
            int n0 = tile * 32;
            __syncthreads();
            for (int i = tid; i < 64*32; i += 256) {
                int d = i & 63, n = i >> 6, ng = n0 + n;
                float v = 0.0f;
                if (ng < NN) {
                    float dsc = __expf(-g_asum[ng]);
                    size_t off = (size_t)ng*C + h*64 + d;
                    v = x[off] + dsc * g_aggr[off];
                }
                sXf[d*33 + n] = v;
            }
            __syncthreads();
            int nb = w * 4;
            ull a0[4], a1[4];
            #pragma unroll
            for (int e = 0; e < 4; e++) {
                a0[e] = h ? 0ull : bi0;
                a1[e] = h ? 0ull : bi1;
            }
            node_gemm_half(sXf, sWu2, lane, nb, a0, a1);
            #pragma unroll 1
            for (int e = 0; e < 4; e++) {
                int n = n0 + nb + e;
                if (n < NN) {
                    float2 f0 = unpack2(a0[e]), f1 = unpack2(a1[e]);
                    float4 o; o.x = f0.x; o.y = f0.y; o.z = f1.x; o.w = f1.y;
                    float* yp = out + (size_t)n*C + 4*lane;
                    if (h) {
                        float4 prev = *(float4*)yp;
                        o.x += prev.x; o.y += prev.y; o.z += prev.z; o.w += prev.w;
                    }
                    *(float4*)yp = o;
                }
            }
        }
    }
}

// ---------------- host launcher ----------------------------------------------
extern "C" void kernel_launch(void* const* d_in, const int* in_sizes, int n_in,
                              void* d_out, int out_size) {
    const float* x   = (const float*)d_in[0];
    const int*   ei  = (const int*  )d_in[1];
    const float* ea  = (const float*)d_in[2];
    const float* Wf  = (const float*)d_in[3];
    const float* bf  = (const float*)d_in[4];
    const float* Wq  = (const float*)d_in[5];
    const float* Wk  = (const float*)d_in[6];
    const float* Wa  = (const float*)d_in[7];
    const float* Wu  = (const float*)d_in[8];
    const float* bu  = (const float*)d_in[9];
    float* out = (float*)d_out;

    (void)in_sizes; (void)n_in; (void)out_size;

    cudaFuncSetAttribute(node_pre_kernel, cudaFuncAttributeMaxDynamicSharedMemorySize, NODE_SMEM);
    cudaFuncSetAttribute(node_out_kernel, cudaFuncAttributeMaxDynamicSharedMemorySize, NODE_SMEM);
    cudaFuncSetAttribute(edge1_kernel,    cudaFuncAttributeMaxDynamicSharedMemorySize, E1_SMEM);

    prep_kernel<<<C, C>>>(Wf, Wq, Wk, Wa);
    zero_kernel<<<(NN*C + 255) / 256, 256>>>();
    node_pre_kernel<<<592, 256, NODE_SMEM>>>(x);
    edge1_kernel<<<592, 256, E1_SMEM>>>(ea, ei, Wf, bf);
    node_out_kernel<<<592, 256, NODE_SMEM>>>(x, Wu, bu, out);
}

// round 11
// speedup vs baseline: 1.1292x; 1.0330x over previous
#include <cuda_runtime.h>

#define NN   50000
#define C    128
#define E    800000
#define EF   65
#define EAC  70
#define ET   64

typedef unsigned long long ull;

// ---------------- scratch (device globals; no allocation allowed) ------------
__device__ float g_A [C*C];           // Wf1 + Wf3
__device__ float g_B [C*C];           // Wf2 - Wf3
__device__ float g_M [C*C];           // scale * Wq diag(Wa) Wk^T
__device__ float g_XA[NN*C];          // x @ A
__device__ float g_XB[NN*C];          // x @ B
__device__ float g_Xm[NN*C];          // x @ M
__device__ float g_asum[NN];          // segment sum of a over src
__device__ float g_aggr[NN*C];        // segment sum of exp(a)*f over src

// ---------------- packed fp32x2 helpers (Blackwell FFMA2) --------------------
__device__ __forceinline__ void fma2(ull &acc, ull a, ull b) {
    asm("fma.rn.f32x2 %0, %1, %2, %0;" : "+l"(acc) : "l"(a), "l"(b));
}
__device__ __forceinline__ ull dup2(float v) {
    unsigned int u = __float_as_uint(v);
    return ((ull)u << 32) | (ull)u;
}
__device__ __forceinline__ ull pack2(float x, float y) {
    return ((ull)__float_as_uint(y) << 32) | (ull)__float_as_uint(x);
}
__device__ __forceinline__ float2 unpack2(ull p) {
    float2 r;
    r.x = __uint_as_float((unsigned int)(p & 0xffffffffull));
    r.y = __uint_as_float((unsigned int)(p >> 32));
    return r;
}
// tanh via exp, saturates correctly at +-1
__device__ __forceinline__ float tanh_fast(float x) {
    float t = __expf(2.0f * x);
    return 1.0f - __fdividef(2.0f, t + 1.0f);
}

// ---------------- K0: fold weights ------------------------------------------
__global__ void prep_kernel(const float* __restrict__ Wf, const float* __restrict__ Wq,
                            const float* __restrict__ Wk, const float* __restrict__ Wa) {
    int d = blockIdx.x;      // 0..127
    int c = threadIdx.x;     // 0..127
    g_A[d*C + c] = Wf[d*C + c]        + Wf[(256+d)*C + c];
    g_B[d*C + c] = Wf[(128+d)*C + c]  - Wf[(256+d)*C + c];
    __shared__ float sWa[C], sWq[C];
    sWa[c] = Wa[c];
    sWq[c] = Wq[d*C + c];
    __syncthreads();
    float acc = 0.0f;
    #pragma unroll 4
    for (int k = 0; k < C; k++) acc += sWq[k] * sWa[k] * Wk[c*C + k];
    g_M[d*C + c] = acc * 0.08838834764831845f;   // 128^-0.5
}

// ---------------- zero accumulators ------------------------------------------
__global__ void zero_kernel() {
    int i = blockIdx.x * blockDim.x + threadIdx.x;
    if (i < NN*C) g_aggr[i] = 0.0f;
    if (i < NN)   g_asum[i] = 0.0f;
}

// ============ K-split node-GEMM scheme ========================================
//   sW4 [64][32] float4 @ 0      32768 B
//   sXf [64][33] f32    @ 32768   8448 B
#define NODE_SW   0
#define NODE_SX   32768
#define NODE_SMEM 41216

__device__ __forceinline__ void node_gemm_half(const float* sXf, const ulonglong2* sWu2,
                                               int lane, int nb, ull a0[4], ull a1[4]) {
    #pragma unroll 8
    for (int d = 0; d < 64; d++) {
        ulonglong2 wv = sWu2[d*32 + lane];
        #pragma unroll
        for (int e = 0; e < 4; e++) {
            ull xv = dup2(sXf[d*33 + nb + e]);
            fma2(a0[e], xv, wv.x);
            fma2(a1[e], xv, wv.y);
        }
    }
}

// ---------------- K1: node precompute XA, XB, Xm -----------------------------
__global__ __launch_bounds__(256, 4) void node_pre_kernel(const float* __restrict__ x) {
    extern __shared__ unsigned char smem[];
    float4*     sW4  = (float4*)(smem + NODE_SW);
    ulonglong2* sWu2 = (ulonglong2*)(smem + NODE_SW);
    float*      sXf  = (float*)(smem + NODE_SX);
    int tid = threadIdx.x, lane = tid & 31, w = tid >> 5;
    const float* Ws[3] = {g_A, g_B, g_M};
    float*       Ys[3] = {g_XA, g_XB, g_Xm};
    const int ntiles = (NN + 31) / 32;
    for (int m = 0; m < 3; m++) {
        const float4* W4 = (const float4*)Ws[m];
        float* Y = Ys[m];
        for (int h = 0; h < 2; h++) {
            __syncthreads();
            for (int i = tid; i < 64*32; i += 256) {
                int dd = i >> 5, l = i & 31;
                sW4[i] = W4[(h*64 + dd)*32 + l];
            }
            for (int tile = blockIdx.x; tile < ntiles; tile += gridDim.x) {
                int n0 = tile * 32;
                __syncthreads();
                for (int i = tid; i < 64*32; i += 256) {
                    int d = i & 63, n = i >> 6, ng = n0 + n;
                    sXf[d*33 + n] = (ng < NN) ? x[(size_t)ng*C + h*64 + d] : 0.0f;
                }
                __syncthreads();
                int nb = w * 4;
                ull a0[4] = {0,0,0,0}, a1[4] = {0,0,0,0};
                node_gemm_half(sXf, sWu2, lane, nb, a0, a1);
                #pragma unroll 1
                for (int e = 0; e < 4; e++) {
                    int n = n0 + nb + e;
                    if (n < NN) {
                        float2 f0 = unpack2(a0[e]), f1 = unpack2(a1[e]);
                        float4 o; o.x = f0.x; o.y = f0.y; o.z = f1.x; o.w = f1.y;
                        float* yp = Y + (size_t)n*C + 4*lane;
                        if (h) {
                            float4 prev = *(float4*)yp;
                            o.x += prev.x; o.y += prev.y; o.z += prev.z; o.w += prev.w;
                        }
                        *(float4*)yp = o;
                    }
                }
            }
        }
    }
}

// ---------------- K2: edge pass — f, a, scatter exp(a)*f and a ----------------
// 256 thr (8 warps), 64 edges/tile, warp = 8 edges (4 edge-pairs) x 128 ch.
//   sW4  [65][32] float4  @ 0      33280 B
//   sEa  [65][66] float   @ 33280  17160 B  (u64 col p = edge pair {2p,2p+1})
//   sBf4 [32]  float4     @ 50448    512 B
//   sIdx [128] int        @ 50960    512 B
#define E1_SW   0
#define E1_SEA  33280
#define E1_SBF  50448
#define E1_SIDX 50960
#define E1_SMEM 51472

__global__ __launch_bounds__(256, 4) void edge1_kernel(const float* __restrict__ ea,
                                                       const int*   __restrict__ ei,
                                                       const float* __restrict__ Wf,
                                                       const float* __restrict__ bf) {
    extern __shared__ unsigned char smem[];
    float4*     sW4  = (float4*)(smem + E1_SW);
    ull*        sEa2 = (ull*)(smem + E1_SEA);
    float*      sEaF = (float*)(smem + E1_SEA);
    float4*     sBf4 = (float4*)(smem + E1_SBF);
    int*        sIdx = (int*)(smem + E1_SIDX);
    int tid = threadIdx.x, lane = tid & 31, w = tid >> 5;

    for (int i = tid; i < EF*32; i += 256) {
        int d = i >> 5, l = i & 31;
        sW4[i] = *(const float4*)(Wf + (size_t)(3*C + d)*C + 4*l);
    }
    if (tid < 32) sBf4[tid] = *(const float4*)(bf + 4*tid);
    __syncthreads();
    float4 b4 = sBf4[lane];
    ull bi0 = dup2(b4.x), bi1 = dup2(b4.y), bi2 = dup2(b4.z), bi3 = dup2(b4.w);

    const int eb = w * 8;                 // this warp's 8 edges within the tile
    const int pb = w * 4;                 // this warp's 4 edge-pairs
    const int ntiles = E / ET;            // 12500
    for (int tile = blockIdx.x; tile < ntiles; tile += gridDim.x) {
        int e0 = tile * ET;
        __syncthreads();
        if (tid < ET)           sIdx[tid] = ei[e0 + tid];
        else if (tid < 2*ET)    sIdx[tid] = ei[E + e0 + tid - ET];
        // coalesced ea staging, streaming (evict-first) loads keep L2 for gathers
        #pragma unroll 1
        for (int i = 0; i < 8; i++) {
            int e = eb + i;
            const float* row = ea + (size_t)(e0 + e)*EAC;
            float2 v = __ldcs((const float2*)(row + 2*lane));
            sEaF[(2*lane)*66   + e] = v.x;
            sEaF[(2*lane+1)*66 + e] = v.y;
            if (lane == 0) sEaF[64*66 + e] = __ldcs(row + 64);
        }
        __syncthreads();

        // GEMM: acc[c][p] = f32x2 accumulator for channel 4*lane+c, edge pair p
        ull a0[4], a1[4], a2[4], a3[4];
        #pragma unroll
        for (int p = 0; p < 4; p++) { a0[p]=bi0; a1[p]=bi1; a2[p]=bi2; a3[p]=bi3; }
        #pragma unroll 5
        for (int d = 0; d < EF; d++) {
            float4 wv = sW4[d*32 + lane];
            ull w0 = dup2(wv.x), w1 = dup2(wv.y), w2 = dup2(wv.z), w3 = dup2(wv.w);
            const ull* er = sEa2 + d*33 + pb;
            #pragma unroll
            for (int p = 0; p < 4; p++) {
                ull ep = er[p];                  // LDS.64 broadcast
                fma2(a0[p], ep, w0);
                fma2(a1[p], ep, w1);
                fma2(a2[p], ep, w2);
                fma2(a3[p], ep, w3);
            }
        }

        // ---- batched epilogue: 2 groups of 4 edges --------------------------
        // Phase A: gathers + ELU + per-lane dot partials (independent, ILP).
        // Phase B: 5 butterfly stages x 4 independent SHFL chains.
        // Phase C: tanh/exp + red/atomic (volatile barriers no longer serialize
        //          the latency chains).
        #pragma unroll
        for (int g = 0; g < 2; g++) {
            float fv[4][4];
            float pd[4];
            int   sg[4];
            #pragma unroll
            for (int i = 0; i < 4; i++) {
                int e = eb + g*4 + i;
                int p = (g*4 + i) >> 1, par = i & 1;
                int s = sIdx[e], t = sIdx[ET + e];
                sg[i] = s;
                float4 xa = __ldg((const float4*)(g_XA + (size_t)s*C + 4*lane));
                float4 xb = __ldg((const float4*)(g_XB + (size_t)t*C + 4*lane));
                float4 xm = __ldg((const float4*)(g_Xm + (size_t)s*C + 4*lane));
                float2 c0 = unpack2(a0[p]), c1 = unpack2(a1[p]);
                float2 c2 = unpack2(a2[p]), c3 = unpack2(a3[p]);
                float v0 = (par ? c0.y : c0.x) + xa.x + xb.x;
                float v1 = (par ? c1.y : c1.x) + xa.y + xb.y;
                float v2 = (par ? c2.y : c2.x) + xa.z + xb.z;
                float v3 = (par ? c3.y : c3.x) + xa.w + xb.w;
                v0 = v0 > 0.0f ? v0 : __expf(v0) - 1.0f;
                v1 = v1 > 0.0f ? v1 : __expf(v1) - 1.0f;
                v2 = v2 > 0.0f ? v2 : __expf(v2) - 1.0f;
                v3 = v3 > 0.0f ? v3 : __expf(v3) - 1.0f;
                float msk = (sEaF[e] < 8.0f) ? 1.0f : 0.0f;
                v0 *= msk; v1 *= msk; v2 *= msk; v3 *= msk;
                fv[i][0] = v0; fv[i][1] = v1; fv[i][2] = v2; fv[i][3] = v3;
                pd[i] = v0*xm.x + v1*xm.y + v2*xm.z + v3*xm.w;
            }
            #pragma unroll
            for (int off = 16; off; off >>= 1) {
                #pragma unroll
                for (int i = 0; i < 4; i++)
                    pd[i] += __shfl_xor_sync(0xffffffffu, pd[i], off);
            }
            float av[4], sc[4];
            #pragma unroll
            for (int i = 0; i < 4; i++) {
                av[i] = tanh_fast(pd[i]);
                sc[i] = __expf(av[i]);
            }
            #pragma unroll
            for (int i = 0; i < 4; i++) {
                asm volatile("red.global.add.v4.f32 [%0], {%1, %2, %3, %4};"
                             :: "l"(g_aggr + (size_t)sg[i]*C + 4*lane),
                                "f"(sc[i]*fv[i][0]), "f"(sc[i]*fv[i][1]),
                                "f"(sc[i]*fv[i][2]), "f"(sc[i]*fv[i][3])
                             : "memory");
                if (lane == 0) atomicAdd(&g_asum[sg[i]], av[i]);
            }
        }
    }
}

// ---------------- K4: out = (x + exp(-asum)*aggr) @ Wu + bu ------------------
__global__ __launch_bounds__(256, 4) void node_out_kernel(const float* __restrict__ x,
                                                          const float* __restrict__ Wu,
                                                          const float* __restrict__ bu,
                                                          float* __restrict__ out) {
    extern __shared__ unsigned char smem[];
    float4*     sW4  = (float4*)(smem + NODE_SW);
    ulonglong2* sWu2 = (ulonglong2*)(smem + NODE_SW);
    float*      sXf  = (float*)(smem + NODE_SX);
    int tid = threadIdx.x, lane = tid & 31, w = tid >> 5;
    const float4* W4 = (const float4*)Wu;
    float4 b4 = *(const float4*)(bu + 4*lane);
    ull bi0 = pack2(b4.x, b4.y), bi1 = pack2(b4.z, b4.w);
    const int ntiles = (NN + 31) / 32;
    for (int h = 0; h < 2; h++) {
        __syncthreads();
        for (int i = tid; i < 64*32; i += 256) {
            int dd = i >> 5, l = i & 31;
            sW4[i] = W4[(h*64 + dd)*32 + l];
        }
        for (int tile = blockIdx.x; tile < ntiles; tile += gridDim.x) {
            int n0 = tile * 32;
            __syncthreads();
            for (int i = tid; i < 64*32; i += 256) {
                int d = i & 63, n = i >> 6, ng = n0 + n;
                float v = 0.0f;
                if (ng < NN) {
                    float dsc = __expf(-g_asum[ng]);
                    size_t off = (size_t)ng*C + h*64 + d;
                    v = x[off] + dsc * g_aggr[off];
                }
                sXf[d*33 + n] = v;
            }
            __syncthreads();
            int nb = w * 4;
            ull a0[4], a1[4];
            #pragma unroll
            for (int e = 0; e < 4; e++) {
                a0[e] = h ? 0ull : bi0;
                a1[e] = h ? 0ull : bi1;
            }
            node_gemm_half(sXf, sWu2, lane, nb, a0, a1);
            #pragma unroll 1
            for (int e = 0; e < 4; e++) {
                int n = n0 + nb + e;
                if (n < NN) {
                    float2 f0 = unpack2(a0[e]), f1 = unpack2(a1[e]);
                    float4 o; o.x = f0.x; o.y = f0.y; o.z = f1.x; o.w = f1.y;
                    float* yp = out + (size_t)n*C + 4*lane;
                    if (h) {
                        float4 prev = *(float4*)yp;
                        o.x += prev.x; o.y += prev.y; o.z += prev.z; o.w += prev.w;
                    }
                    *(float4*)yp = o;
                }
            }
        }
    }
}

// ---------------- host launcher ----------------------------------------------
extern "C" void kernel_launch(void* const* d_in, const int* in_sizes, int n_in,
                              void* d_out, int out_size) {
    const float* x   = (const float*)d_in[0];
    const int*   ei  = (const int*  )d_in[1];
    const float* ea  = (const float*)d_in[2];
    const float* Wf  = (const float*)d_in[3];
    const float* bf  = (const float*)d_in[4];
    const float* Wq  = (const float*)d_in[5];
    const float* Wk  = (const float*)d_in[6];
    const float* Wa  = (const float*)d_in[7];
    const float* Wu  = (const float*)d_in[8];
    const float* bu  = (const float*)d_in[9];
    float* out = (float*)d_out;

    (void)in_sizes; (void)n_in; (void)out_size;

    cudaFuncSetAttribute(node_pre_kernel, cudaFuncAttributeMaxDynamicSharedMemorySize, NODE_SMEM);
    cudaFuncSetAttribute(node_out_kernel, cudaFuncAttributeMaxDynamicSharedMemorySize, NODE_SMEM);
    cudaFuncSetAttribute(edge1_kernel,    cudaFuncAttributeMaxDynamicSharedMemorySize, E1_SMEM);

    prep_kernel<<<C, C>>>(Wf, Wq, Wk, Wa);
    zero_kernel<<<(NN*C + 255) / 256, 256>>>();
    node_pre_kernel<<<592, 256, NODE_SMEM>>>(x);
    edge1_kernel<<<592, 256, E1_SMEM>>>(ea, ei, Wf, bf);
    node_out_kernel<<<592, 256, NODE_SMEM>>>(x, Wu, bu, out);
}